// round 12
// baseline (speedup 1.0000x reference)
#include <cuda_runtime.h>

#define T_N 1024
#define B_N 256
#define H_N 20
#define B3  (B_N * 3)
#define OFF (T_N * B3)

__device__ float g_me[T_N];

// ---------------------------------------------------------------------------
// Kernel A: me[i] = sigmoid(MLP(t[i]))
// ---------------------------------------------------------------------------
__device__ __forceinline__ float tanh_fast(float x) {
    float e = __expf(2.0f * x);
    return 1.0f - 2.0f / (e + 1.0f);
}

__global__ void mlp_kernel(const float* __restrict__ t,
                           const float* __restrict__ w1, const float* __restrict__ b1,
                           const float* __restrict__ w2, const float* __restrict__ b2,
                           const float* __restrict__ w3, const float* __restrict__ b3,
                           const float* __restrict__ w4, const float* __restrict__ b4) {
    int i = blockIdx.x * blockDim.x + threadIdx.x;
    if (i >= T_N) return;
    float tv = t[i];

    float h1[H_N], h2[H_N];
    #pragma unroll
    for (int o = 0; o < H_N; o++)
        h1[o] = tanh_fast(tv * w1[o] + b1[o]);

    #pragma unroll
    for (int o = 0; o < H_N; o++) {
        float acc = b2[o];
        #pragma unroll
        for (int m = 0; m < H_N; m++)
            acc += h1[m] * w2[m * H_N + o];
        h2[o] = tanh_fast(acc);
    }

    #pragma unroll
    for (int o = 0; o < H_N; o++) {
        float acc = b3[o];
        #pragma unroll
        for (int m = 0; m < H_N; m++)
            acc += h2[m] * w3[m * H_N + o];
        h1[o] = tanh_fast(acc);
    }

    float acc = b4[0];
    #pragma unroll
    for (int m = 0; m < H_N; m++)
        acc += h1[m] * w4[m];

    g_me[i] = 1.0f / (1.0f + __expf(-acc));
}

// ---------------------------------------------------------------------------
// Kernel B: one CTA (192 thr = 6 warps) handles TWO batch elements.
//  warp 0    : stepper. Lanes 0-15 run batch 2b, lanes 16-31 run batch 2b+1 —
//              same SIMT instruction stream, per-half data. 16-slot register
//              ring; branch/shuffle/STG-free inner loop.
//  warps 1..4: far-field helpers — 2 warps per batch, float4 k-chunks x 8
//              targets via 12-float rs window; transpose-reduce; atomicAdd.
//  warp 5    : writer — flushes both batches' staged outputs; zeroes Pf ahead.
// rs[d] = me[T-d];  integ_n = dt * sum_{k<n} rs[n-k]*Ih[k].
// ---------------------------------------------------------------------------

#define STEP(nv, PHI, SLOT, PFV) {                                         \
    const int n_ = (nv);                                                    \
    const float integ = fmaf(dt, a[SLOT], (PFV));                           \
    const float bSI = beta * S * I;                                         \
    const float gI  = gamma * I;                                            \
    const float d0 = integ - bSI;                                           \
    const float d1 = bSI - gI;                                              \
    const float d2 = gI - integ;                                            \
    S = fmaf(d0, dt, S);                                                    \
    I = fmaf(d1, dt, I);                                                    \
    R = fmaf(d2, dt, R);                                                    \
    if (lw) IhB[n_] = I;                                                    \
    if (lw) { stg[PHI][0] = make_float4(S, I, R, d0);                       \
              stg[PHI][1] = make_float4(d1, d2, 0.f, 0.f); }                \
    _Pragma("unroll")                                                       \
    for (int d_ = 1; d_ <= 15 - (PHI); ++d_) {                              \
        const int s_ = ((SLOT) + d_) & 15;                                  \
        if ((PHI) == 0 && d_ >= 8) a[s_] = rsr[d_] * I;                     \
        else                       a[s_] = fmaf(rsr[d_], I, a[s_]);         \
    }                                                                       \
}

#define INTERVAL8(n0, RB)                                                   \
    STEP((n0) + 0, 0, ((RB) + 0), pfa.x)                                    \
    STEP((n0) + 1, 1, ((RB) + 1), pfa.y)                                    \
    STEP((n0) + 2, 2, ((RB) + 2), pfa.z)                                    \
    STEP((n0) + 3, 3, ((RB) + 3), pfa.w)                                    \
    STEP((n0) + 4, 4, ((RB) + 4), pfb.x)                                    \
    STEP((n0) + 5, 5, ((RB) + 5), pfb.y)                                    \
    STEP((n0) + 6, 6, ((RB) + 6), pfb.z)                                    \
    STEP((n0) + 7, 7, ((RB) + 7), pfb.w)

__global__ void __launch_bounds__(192) scan_kernel(
    const float* __restrict__ t,
    const float* __restrict__ y,
    const float* __restrict__ beta_p,
    const float* __restrict__ gamma_p,
    float* __restrict__ out) {

    __shared__ __align__(16) float rs[T_N];
    __shared__ __align__(16) float Ih[2][T_N];
    __shared__ __align__(16) float Pf[2][T_N];
    __shared__ float  Ps[2][2][8][33];     // [batch][helper-pair][target][lane]
    __shared__ float4 stage[2][2][8][2];   // [buf][batch][phase][half]

    const int b    = blockIdx.x;           // 0..127, handles batches 2b, 2b+1
    const int tid  = threadIdx.x;
    const int role = tid >> 5;
    const int lane = tid & 31;

    for (int i = tid; i < T_N; i += 192)
        rs[i] = (i == 0) ? 0.0f : g_me[T_N - i];
    if (tid < 32) Pf[tid >> 4][tid & 15] = 0.0f;  // intervals 0-1: no far field

    const float dt    = t[0] - t[1];
    const float beta  = beta_p[0];
    const float gamma = gamma_p[0];

    // stepper per-lane batch split
    const int  bl  = lane >> 4;            // 0 or 1
    const int  b3  = (2 * b + bl) * 3;     // this half's global batch offset
    const bool lw  = (lane & 15) == 0;     // lanes 0 and 16
    float* const IhB = Ih[bl];

    float a[16];
    float rsr[16];
    float S = 0.f, I = 0.f, R = 0.f;
    if (role == 0) {
        #pragma unroll
        for (int s = 0; s < 16; s++) a[s] = 0.0f;
        S = y[b3 + 0];
        I = y[b3 + 1];
        R = y[b3 + 2];
    }
    __syncthreads();
    if (role == 0) {
        #pragma unroll
        for (int d = 1; d <= 15; d++) rsr[d] = rs[d];
    }

    for (int i = 0; i < 128; ++i) {
        if (role == 0) {
            float4 (*stg)[2] = stage[i & 1][bl];
            if (i == 0) {
                if (lw) {
                    IhB[0] = I;
                    out[b3 + 0] = S; out[b3 + 1] = I; out[b3 + 2] = R;
                    const int zb = OFF + (T_N - 1) * B3 + b3;
                    out[zb + 0] = 0.0f; out[zb + 1] = 0.0f; out[zb + 2] = 0.0f;
                }
                #pragma unroll
                for (int d = 1; d <= 15; d++) a[d & 15] = rsr[d] * I;
                STEP(1, 1, 1, 0.0f) STEP(2, 2, 2, 0.0f) STEP(3, 3, 3, 0.0f)
                STEP(4, 4, 4, 0.0f) STEP(5, 5, 5, 0.0f) STEP(6, 6, 6, 0.0f)
                STEP(7, 7, 7, 0.0f)
            } else {
                const float4 pfa = *(const float4*)&Pf[bl][8 * i];
                const float4 pfb = *(const float4*)&Pf[bl][8 * i + 4];
                if (i & 1) { INTERVAL8(8 * i, 8) }
                else       { INTERVAL8(8 * i, 0) }
            }
        } else if (role <= 4) {
            // far field: targets [8(i+1), 8(i+1)+7] over k < 8i
            const int hb = (role - 1) >> 1;   // batch half
            const int hp = (role - 1) & 1;    // pair index within batch
            const int T0 = 8 * i + 8;
            if (i >= 1 && T0 < T_N) {
                const int nch = 2 * i;         // float4 chunks of k
                const float* IhH = Ih[hb];
                float acc[8];
                #pragma unroll
                for (int tt = 0; tt < 8; tt++) acc[tt] = 0.0f;
                for (int c = hp * 32 + lane; c < nch; c += 64) {
                    const int k0 = c << 2;
                    const float4 ih = *(const float4*)&IhH[k0];
                    const float* wp = &rs[T0 - k0 - 4];
                    float w[12];
                    *(float4*)&w[0] = *(const float4*)&wp[0];
                    *(float4*)&w[4] = *(const float4*)&wp[4];
                    *(float4*)&w[8] = *(const float4*)&wp[8];
                    #pragma unroll
                    for (int tt = 0; tt < 8; tt++) {
                        float s0 = fmaf(w[tt + 4], ih.x, acc[tt]);
                        s0 = fmaf(w[tt + 3], ih.y, s0);
                        s0 = fmaf(w[tt + 2], ih.z, s0);
                        acc[tt] = fmaf(w[tt + 1], ih.w, s0);
                    }
                }
                #pragma unroll
                for (int tt = 0; tt < 8; tt++) Ps[hb][hp][tt][lane] = acc[tt];
                __syncwarp();
                const int ttr = lane >> 2, pp = lane & 3;
                const float* q = &Ps[hb][hp][ttr][pp * 8];
                float s0 = ((q[0] + q[1]) + (q[2] + q[3]))
                         + ((q[4] + q[5]) + (q[6] + q[7]));
                s0 += __shfl_xor_sync(0xffffffffu, s0, 1);
                s0 += __shfl_xor_sync(0xffffffffu, s0, 2);
                if (pp == 0) atomicAdd(&Pf[hb][T0 + ttr], dt * s0);
            }
        } else {
            // writer: zero Pf two intervals ahead (both batches); flush prev
            const int z = 8 * i + 16;
            if (z < T_N && lane >= 16)
                Pf[(lane >> 3) & 1][z + (lane & 7)] = 0.0f;
            if (i >= 1 && lane < 24) {
                const int j  = i - 1;
                const int ph = lane / 3;
                const int c  = lane % 3;
                const int n  = 8 * j + ph;
                if (n >= 1) {
                    #pragma unroll
                    for (int bb = 0; bb < 2; bb++) {
                        const float* sp = (const float*)&stage[j & 1][bb][ph][0];
                        const int bw = (2 * b + bb) * 3;
                        out[n * B3 + bw + c]             = sp[c];
                        out[OFF + (n - 1) * B3 + bw + c] = sp[3 + c];
                    }
                }
            }
        }
        __syncthreads();
    }

    // final flush of interval 127 (both batches)
    if (role == 5 && lane < 24) {
        const int ph = lane / 3;
        const int c  = lane % 3;
        const int n  = 8 * 127 + ph;
        #pragma unroll
        for (int bb = 0; bb < 2; bb++) {
            const float* sp = (const float*)&stage[127 & 1][bb][ph][0];
            const int bw = (2 * b + bb) * 3;
            out[n * B3 + bw + c]             = sp[c];
            out[OFF + (n - 1) * B3 + bw + c] = sp[3 + c];
        }
    }
}

// ---------------------------------------------------------------------------
// Launch
// ---------------------------------------------------------------------------
extern "C" void kernel_launch(void* const* d_in, const int* in_sizes, int n_in,
                              void* d_out, int out_size) {
    const float* t     = (const float*)d_in[0];
    const float* y     = (const float*)d_in[1];
    const float* w1    = (const float*)d_in[2];
    const float* b1    = (const float*)d_in[3];
    const float* w2    = (const float*)d_in[4];
    const float* b2    = (const float*)d_in[5];
    const float* w3    = (const float*)d_in[6];
    const float* b3    = (const float*)d_in[7];
    const float* w4    = (const float*)d_in[8];
    const float* b4    = (const float*)d_in[9];
    const float* beta  = (const float*)d_in[10];
    const float* gamma = (const float*)d_in[11];
    float* out = (float*)d_out;

    mlp_kernel<<<16, 64>>>(t, w1, b1, w2, b2, w3, b3, w4, b4);
    scan_kernel<<<B_N / 2, 192>>>(t, y, beta, gamma, out);
}

// round 13
// speedup vs baseline: 1.1639x; 1.1639x over previous
#include <cuda_runtime.h>

#define T_N 1024
#define B_N 256
#define H_N 20
#define B3  (B_N * 3)
#define OFF (T_N * B3)

__device__ float g_me[T_N];

// ---------------------------------------------------------------------------
// Kernel A: me[i] = sigmoid(MLP(t[i]))
// ---------------------------------------------------------------------------
__device__ __forceinline__ float tanh_fast(float x) {
    float e = __expf(2.0f * x);
    return 1.0f - 2.0f / (e + 1.0f);
}

__global__ void mlp_kernel(const float* __restrict__ t,
                           const float* __restrict__ w1, const float* __restrict__ b1,
                           const float* __restrict__ w2, const float* __restrict__ b2,
                           const float* __restrict__ w3, const float* __restrict__ b3,
                           const float* __restrict__ w4, const float* __restrict__ b4) {
    int i = blockIdx.x * blockDim.x + threadIdx.x;
    if (i >= T_N) return;
    float tv = t[i];

    float h1[H_N], h2[H_N];
    #pragma unroll
    for (int o = 0; o < H_N; o++)
        h1[o] = tanh_fast(tv * w1[o] + b1[o]);

    #pragma unroll
    for (int o = 0; o < H_N; o++) {
        float acc = b2[o];
        #pragma unroll
        for (int m = 0; m < H_N; m++)
            acc += h1[m] * w2[m * H_N + o];
        h2[o] = tanh_fast(acc);
    }

    #pragma unroll
    for (int o = 0; o < H_N; o++) {
        float acc = b3[o];
        #pragma unroll
        for (int m = 0; m < H_N; m++)
            acc += h2[m] * w3[m * H_N + o];
        h1[o] = tanh_fast(acc);
    }

    float acc = b4[0];
    #pragma unroll
    for (int m = 0; m < H_N; m++)
        acc += h1[m] * w4[m];

    g_me[i] = 1.0f / (1.0f + __expf(-acc));
}

// ---------------------------------------------------------------------------
// Kernel B: one CTA (320 thr = 10 warps) handles TWO batch elements.
//  warp 0    : stepper. Lanes 0-15 run batch 2b, lanes 16-31 run batch 2b+1 —
//              same SIMT stream, per-half data. 16-slot register ring.
//  warps 1..8: far-field helpers — FOUR warps per batch (k-stride 128),
//              float4 k-chunks x 8 targets, 12-float rs window,
//              transpose-reduce, atomicAdd into Pf.
//  warp 9    : writer — flushes both batches' staged outputs; zeroes Pf ahead.
// rs[d] = me[T-d];  integ_n = dt * sum_{k<n} rs[n-k]*Ih[k].
// ---------------------------------------------------------------------------

#define STEP(nv, PHI, SLOT, PFV) {                                         \
    const int n_ = (nv);                                                    \
    const float integ = fmaf(dt, a[SLOT], (PFV));                           \
    const float bSI = beta * S * I;                                         \
    const float gI  = gamma * I;                                            \
    const float d0 = integ - bSI;                                           \
    const float d1 = bSI - gI;                                              \
    const float d2 = gI - integ;                                            \
    S = fmaf(d0, dt, S);                                                    \
    I = fmaf(d1, dt, I);                                                    \
    R = fmaf(d2, dt, R);                                                    \
    if (lw) IhB[n_] = I;                                                    \
    if (lw) { stg[PHI][0] = make_float4(S, I, R, d0);                       \
              stg[PHI][1] = make_float4(d1, d2, 0.f, 0.f); }                \
    _Pragma("unroll")                                                       \
    for (int d_ = 1; d_ <= 15 - (PHI); ++d_) {                              \
        const int s_ = ((SLOT) + d_) & 15;                                  \
        if ((PHI) == 0 && d_ >= 8) a[s_] = rsr[d_] * I;                     \
        else                       a[s_] = fmaf(rsr[d_], I, a[s_]);         \
    }                                                                       \
}

#define INTERVAL8(n0, RB)                                                   \
    STEP((n0) + 0, 0, ((RB) + 0), pfa.x)                                    \
    STEP((n0) + 1, 1, ((RB) + 1), pfa.y)                                    \
    STEP((n0) + 2, 2, ((RB) + 2), pfa.z)                                    \
    STEP((n0) + 3, 3, ((RB) + 3), pfa.w)                                    \
    STEP((n0) + 4, 4, ((RB) + 4), pfb.x)                                    \
    STEP((n0) + 5, 5, ((RB) + 5), pfb.y)                                    \
    STEP((n0) + 6, 6, ((RB) + 6), pfb.z)                                    \
    STEP((n0) + 7, 7, ((RB) + 7), pfb.w)

__global__ void __launch_bounds__(320) scan_kernel(
    const float* __restrict__ t,
    const float* __restrict__ y,
    const float* __restrict__ beta_p,
    const float* __restrict__ gamma_p,
    float* __restrict__ out) {

    __shared__ __align__(16) float rs[T_N];
    __shared__ __align__(16) float Ih[2][T_N];
    __shared__ __align__(16) float Pf[2][T_N];
    __shared__ float  Ps[2][4][8][33];     // [batch][helper][target][lane]
    __shared__ float4 stage[2][2][8][2];   // [buf][batch][phase][half]

    const int b    = blockIdx.x;           // 0..127, handles batches 2b, 2b+1
    const int tid  = threadIdx.x;
    const int role = tid >> 5;
    const int lane = tid & 31;

    for (int i = tid; i < T_N; i += 320)
        rs[i] = (i == 0) ? 0.0f : g_me[T_N - i];
    if (tid < 32) Pf[tid >> 4][tid & 15] = 0.0f;  // intervals 0-1: no far field

    const float dt    = t[0] - t[1];
    const float beta  = beta_p[0];
    const float gamma = gamma_p[0];

    // stepper per-lane batch split
    const int  bl  = lane >> 4;            // 0 or 1
    const int  b3  = (2 * b + bl) * 3;     // this half's global batch offset
    const bool lw  = (lane & 15) == 0;     // lanes 0 and 16
    float* const IhB = Ih[bl];

    float a[16];
    float rsr[16];
    float S = 0.f, I = 0.f, R = 0.f;
    if (role == 0) {
        #pragma unroll
        for (int s = 0; s < 16; s++) a[s] = 0.0f;
        S = y[b3 + 0];
        I = y[b3 + 1];
        R = y[b3 + 2];
    }
    __syncthreads();
    if (role == 0) {
        #pragma unroll
        for (int d = 1; d <= 15; d++) rsr[d] = rs[d];
    }

    for (int i = 0; i < 128; ++i) {
        if (role == 0) {
            float4 (*stg)[2] = stage[i & 1][bl];
            if (i == 0) {
                if (lw) {
                    IhB[0] = I;
                    out[b3 + 0] = S; out[b3 + 1] = I; out[b3 + 2] = R;
                    const int zb = OFF + (T_N - 1) * B3 + b3;
                    out[zb + 0] = 0.0f; out[zb + 1] = 0.0f; out[zb + 2] = 0.0f;
                }
                #pragma unroll
                for (int d = 1; d <= 15; d++) a[d & 15] = rsr[d] * I;
                STEP(1, 1, 1, 0.0f) STEP(2, 2, 2, 0.0f) STEP(3, 3, 3, 0.0f)
                STEP(4, 4, 4, 0.0f) STEP(5, 5, 5, 0.0f) STEP(6, 6, 6, 0.0f)
                STEP(7, 7, 7, 0.0f)
            } else {
                const float4 pfa = *(const float4*)&Pf[bl][8 * i];
                const float4 pfb = *(const float4*)&Pf[bl][8 * i + 4];
                if (i & 1) { INTERVAL8(8 * i, 8) }
                else       { INTERVAL8(8 * i, 0) }
            }
        } else if (role <= 8) {
            // far field: targets [8(i+1), 8(i+1)+7] over k < 8i
            const int hb = (role - 1) >> 2;   // batch half (0/1)
            const int hp = (role - 1) & 3;    // helper index within batch (0..3)
            const int T0 = 8 * i + 8;
            if (i >= 1 && T0 < T_N) {
                const int nch = 2 * i;         // float4 chunks of k
                const float* IhH = Ih[hb];
                float acc[8];
                #pragma unroll
                for (int tt = 0; tt < 8; tt++) acc[tt] = 0.0f;
                for (int c = hp * 32 + lane; c < nch; c += 128) {
                    const int k0 = c << 2;
                    const float4 ih = *(const float4*)&IhH[k0];
                    const float* wp = &rs[T0 - k0 - 4];
                    float w[12];
                    *(float4*)&w[0] = *(const float4*)&wp[0];
                    *(float4*)&w[4] = *(const float4*)&wp[4];
                    *(float4*)&w[8] = *(const float4*)&wp[8];
                    #pragma unroll
                    for (int tt = 0; tt < 8; tt++) {
                        float s0 = fmaf(w[tt + 4], ih.x, acc[tt]);
                        s0 = fmaf(w[tt + 3], ih.y, s0);
                        s0 = fmaf(w[tt + 2], ih.z, s0);
                        acc[tt] = fmaf(w[tt + 1], ih.w, s0);
                    }
                }
                #pragma unroll
                for (int tt = 0; tt < 8; tt++) Ps[hb][hp][tt][lane] = acc[tt];
                __syncwarp();
                const int ttr = lane >> 2, pp = lane & 3;
                const float* q = &Ps[hb][hp][ttr][pp * 8];
                float s0 = ((q[0] + q[1]) + (q[2] + q[3]))
                         + ((q[4] + q[5]) + (q[6] + q[7]));
                s0 += __shfl_xor_sync(0xffffffffu, s0, 1);
                s0 += __shfl_xor_sync(0xffffffffu, s0, 2);
                if (pp == 0) atomicAdd(&Pf[hb][T0 + ttr], dt * s0);
            }
        } else {
            // writer: zero Pf two intervals ahead (both batches); flush prev
            const int z = 8 * i + 16;
            if (z < T_N && lane >= 16)
                Pf[(lane >> 3) & 1][z + (lane & 7)] = 0.0f;
            if (i >= 1 && lane < 24) {
                const int j  = i - 1;
                const int ph = lane / 3;
                const int c  = lane % 3;
                const int n  = 8 * j + ph;
                if (n >= 1) {
                    #pragma unroll
                    for (int bb = 0; bb < 2; bb++) {
                        const float* sp = (const float*)&stage[j & 1][bb][ph][0];
                        const int bw = (2 * b + bb) * 3;
                        out[n * B3 + bw + c]             = sp[c];
                        out[OFF + (n - 1) * B3 + bw + c] = sp[3 + c];
                    }
                }
            }
        }
        __syncthreads();
    }

    // final flush of interval 127 (both batches)
    if (role == 9 && lane < 24) {
        const int ph = lane / 3;
        const int c  = lane % 3;
        const int n  = 8 * 127 + ph;
        #pragma unroll
        for (int bb = 0; bb < 2; bb++) {
            const float* sp = (const float*)&stage[127 & 1][bb][ph][0];
            const int bw = (2 * b + bb) * 3;
            out[n * B3 + bw + c]             = sp[c];
            out[OFF + (n - 1) * B3 + bw + c] = sp[3 + c];
        }
    }
}

// ---------------------------------------------------------------------------
// Launch
// ---------------------------------------------------------------------------
extern "C" void kernel_launch(void* const* d_in, const int* in_sizes, int n_in,
                              void* d_out, int out_size) {
    const float* t     = (const float*)d_in[0];
    const float* y     = (const float*)d_in[1];
    const float* w1    = (const float*)d_in[2];
    const float* b1    = (const float*)d_in[3];
    const float* w2    = (const float*)d_in[4];
    const float* b2    = (const float*)d_in[5];
    const float* w3    = (const float*)d_in[6];
    const float* b3    = (const float*)d_in[7];
    const float* w4    = (const float*)d_in[8];
    const float* b4    = (const float*)d_in[9];
    const float* beta  = (const float*)d_in[10];
    const float* gamma = (const float*)d_in[11];
    float* out = (float*)d_out;

    mlp_kernel<<<16, 64>>>(t, w1, b1, w2, b2, w3, b3, w4, b4);
    scan_kernel<<<B_N / 2, 320>>>(t, y, beta, gamma, out);
}